// round 1
// baseline (speedup 1.0000x reference)
#include <cuda_runtime.h>
#include <math.h>

#define Hdim   768
#define FFdim  3072
#define NLAY   12
#define NHEADS 12
#define DHEAD  64
#define BATCH  4
#define SEQ    512
#define MTOK   (BATCH*SEQ)   // 2048
#define NEnt   12
#define NRel   13

// ---------------- scratch (static device globals; no allocation) -------------
__device__ float g_x[MTOK*Hdim];
__device__ float g_q[MTOK*Hdim];
__device__ float g_k[MTOK*Hdim];
__device__ float g_v[MTOK*Hdim];
__device__ float g_ctx[MTOK*Hdim];
__device__ float g_ffn[MTOK*FFdim];
__device__ float g_scores[(size_t)BATCH*NHEADS*SEQ*SEQ];
__device__ float g_pi[MTOK*NRel];
__device__ float g_pj[MTOK*NRel];
__device__ float g_abias[BATCH*SEQ];

// ---------------- embedding + LayerNorm --------------------------------------
__global__ __launch_bounds__(256) void embed_ln_kernel(
    const int* __restrict__ ids, const float* __restrict__ ew,
    const float* __restrict__ ep, const float* __restrict__ et,
    const float* __restrict__ g, const float* __restrict__ b)
{
    int t = blockIdx.x;
    int s = t & (SEQ - 1);
    int id = ids[t];
    int tid = threadIdx.x;
    float vals[3];
    float sum = 0.f;
#pragma unroll
    for (int i = 0; i < 3; i++) {
        int c = tid + i * 256;
        vals[i] = ew[(size_t)id * Hdim + c] + ep[(size_t)s * Hdim + c] + et[c];
        sum += vals[i];
    }
    __shared__ float red[256];
    red[tid] = sum; __syncthreads();
    for (int o = 128; o; o >>= 1) { if (tid < o) red[tid] += red[tid + o]; __syncthreads(); }
    float mean = red[0] * (1.f / Hdim);
    __syncthreads();
    float sq = 0.f;
#pragma unroll
    for (int i = 0; i < 3; i++) { float d = vals[i] - mean; sq += d * d; }
    red[tid] = sq; __syncthreads();
    for (int o = 128; o; o >>= 1) { if (tid < o) red[tid] += red[tid + o]; __syncthreads(); }
    float rstd = rsqrtf(red[0] * (1.f / Hdim) + 1e-12f);
#pragma unroll
    for (int i = 0; i < 3; i++) {
        int c = tid + i * 256;
        g_x[(size_t)t * Hdim + c] = (vals[i] - mean) * rstd * g[c] + b[c];
    }
}

// ---------------- residual add + LayerNorm (in-place on x) -------------------
__global__ __launch_bounds__(256) void add_ln_kernel(
    float* __restrict__ x, const float* __restrict__ y,
    const float* __restrict__ g, const float* __restrict__ b)
{
    int t = blockIdx.x;
    int tid = threadIdx.x;
    float vals[3];
    float sum = 0.f;
#pragma unroll
    for (int i = 0; i < 3; i++) {
        int c = tid + i * 256;
        vals[i] = x[(size_t)t * Hdim + c] + y[(size_t)t * Hdim + c];
        sum += vals[i];
    }
    __shared__ float red[256];
    red[tid] = sum; __syncthreads();
    for (int o = 128; o; o >>= 1) { if (tid < o) red[tid] += red[tid + o]; __syncthreads(); }
    float mean = red[0] * (1.f / Hdim);
    __syncthreads();
    float sq = 0.f;
#pragma unroll
    for (int i = 0; i < 3; i++) { float d = vals[i] - mean; sq += d * d; }
    red[tid] = sq; __syncthreads();
    for (int o = 128; o; o >>= 1) { if (tid < o) red[tid] += red[tid + o]; __syncthreads(); }
    float rstd = rsqrtf(red[0] * (1.f / Hdim) + 1e-12f);
#pragma unroll
    for (int i = 0; i < 3; i++) {
        int c = tid + i * 256;
        x[(size_t)t * Hdim + c] = (vals[i] - mean) * rstd * g[c] + b[c];
    }
}

// ---------------- generic SGEMM: C = A(MxK) @ W(KxN) + bias [+ gelu] ---------
// BM=128, BN=64, BK=16, 256 threads, each thread 8x4 outputs.
__global__ __launch_bounds__(256) void sgemm_kernel(
    const float* __restrict__ A, const float* __restrict__ W,
    const float* __restrict__ bias, float* __restrict__ C,
    int M, int N, int K, int act)
{
    __shared__ float As[16][128];
    __shared__ float Bs[16][64];
    int tid = threadIdx.x;
    int tx = tid & 15;       // n dir
    int ty = tid >> 4;       // m dir
    int m0 = blockIdx.y * 128;
    int n0 = blockIdx.x * 64;

    float acc[8][4];
#pragma unroll
    for (int i = 0; i < 8; i++)
#pragma unroll
        for (int j = 0; j < 4; j++) acc[i][j] = 0.f;

    for (int k0 = 0; k0 < K; k0 += 16) {
        // A tile: 128x16 = 512 float4, 2 per thread; store transposed
#pragma unroll
        for (int u = 0; u < 2; u++) {
            int f = tid * 2 + u;          // 0..511
            int row = f >> 2;
            int kk4 = (f & 3) * 4;
            float4 av = *(const float4*)(A + (size_t)(m0 + row) * K + k0 + kk4);
            As[kk4 + 0][row] = av.x;
            As[kk4 + 1][row] = av.y;
            As[kk4 + 2][row] = av.z;
            As[kk4 + 3][row] = av.w;
        }
        // B tile: 16x64 = 256 float4, 1 per thread
        {
            int kk = tid >> 4;
            int nn = (tid & 15) * 4;
            *(float4*)(&Bs[kk][nn]) = *(const float4*)(W + (size_t)(k0 + kk) * N + n0 + nn);
        }
        __syncthreads();
#pragma unroll
        for (int kk = 0; kk < 16; kk++) {
            float4 a0 = *(const float4*)&As[kk][ty * 8];
            float4 a1 = *(const float4*)&As[kk][ty * 8 + 4];
            float4 b0 = *(const float4*)&Bs[kk][tx * 4];
            float a[8] = {a0.x, a0.y, a0.z, a0.w, a1.x, a1.y, a1.z, a1.w};
            float bb[4] = {b0.x, b0.y, b0.z, b0.w};
#pragma unroll
            for (int i = 0; i < 8; i++)
#pragma unroll
                for (int j = 0; j < 4; j++)
                    acc[i][j] = fmaf(a[i], bb[j], acc[i][j]);
        }
        __syncthreads();
    }
#pragma unroll
    for (int i = 0; i < 8; i++) {
        int row = m0 + ty * 8 + i;
#pragma unroll
        for (int j = 0; j < 4; j++) {
            int col = n0 + tx * 4 + j;
            float v = acc[i][j] + bias[col];
            if (act) v = 0.5f * v * (1.0f + erff(v * 0.70710678118654752f));
            C[(size_t)row * N + col] = v;
        }
    }
}

// ---------------- attention-mask bias -----------------------------------------
__global__ void abias_kernel(const int* __restrict__ mask)
{
    int i = blockIdx.x * blockDim.x + threadIdx.x;
    if (i < BATCH * SEQ) g_abias[i] = (1.f - (float)mask[i]) * -10000.f;
}

// ---------------- attention scores: per (b,h) Q(512x64) @ K^T ----------------
__global__ __launch_bounds__(256) void attn_scores_kernel(
    const float* __restrict__ q, const float* __restrict__ k)
{
    __shared__ float Qs[DHEAD][68];
    __shared__ float Ks[DHEAD][68];
    int bh = blockIdx.z;
    int b = bh / NHEADS, h = bh - b * NHEADS;
    int i0 = blockIdx.y * 64, j0 = blockIdx.x * 64;
    int tid = threadIdx.x;
#pragma unroll
    for (int u = 0; u < 4; u++) {
        int f = tid + u * 256;
        int r = f >> 4;
        int d4 = (f & 15) * 4;
        float4 qv = *(const float4*)(q + (size_t)(b * SEQ + i0 + r) * Hdim + h * DHEAD + d4);
        Qs[d4 + 0][r] = qv.x; Qs[d4 + 1][r] = qv.y; Qs[d4 + 2][r] = qv.z; Qs[d4 + 3][r] = qv.w;
        float4 kv = *(const float4*)(k + (size_t)(b * SEQ + j0 + r) * Hdim + h * DHEAD + d4);
        Ks[d4 + 0][r] = kv.x; Ks[d4 + 1][r] = kv.y; Ks[d4 + 2][r] = kv.z; Ks[d4 + 3][r] = kv.w;
    }
    __syncthreads();
    int tx = tid & 15, ty = tid >> 4;
    float acc[4][4];
#pragma unroll
    for (int i = 0; i < 4; i++)
#pragma unroll
        for (int j = 0; j < 4; j++) acc[i][j] = 0.f;
#pragma unroll
    for (int d = 0; d < DHEAD; d++) {
        float4 a = *(const float4*)&Qs[d][ty * 4];
        float4 bb = *(const float4*)&Ks[d][tx * 4];
        float av[4] = {a.x, a.y, a.z, a.w};
        float bv[4] = {bb.x, bb.y, bb.z, bb.w};
#pragma unroll
        for (int i = 0; i < 4; i++)
#pragma unroll
            for (int j = 0; j < 4; j++)
                acc[i][j] = fmaf(av[i], bv[j], acc[i][j]);
    }
#pragma unroll
    for (int i = 0; i < 4; i++) {
        int irow = i0 + ty * 4 + i;
#pragma unroll
        for (int j = 0; j < 4; j++) {
            int jcol = j0 + tx * 4 + j;
            g_scores[((size_t)bh * SEQ + irow) * SEQ + jcol] =
                acc[i][j] * 0.125f + g_abias[b * SEQ + jcol];
        }
    }
}

// ---------------- softmax over rows of 512 ------------------------------------
__global__ __launch_bounds__(256) void softmax_kernel(float* __restrict__ scores)
{
    float* p = scores + (size_t)blockIdx.x * SEQ;
    int tid = threadIdx.x;
    float a = p[tid], b = p[tid + 256];
    __shared__ float red[256];
    red[tid] = fmaxf(a, b); __syncthreads();
    for (int o = 128; o; o >>= 1) { if (tid < o) red[tid] = fmaxf(red[tid], red[tid + o]); __syncthreads(); }
    float m = red[0];
    __syncthreads();
    float e0 = expf(a - m), e1 = expf(b - m);
    red[tid] = e0 + e1; __syncthreads();
    for (int o = 128; o; o >>= 1) { if (tid < o) red[tid] += red[tid + o]; __syncthreads(); }
    float inv = 1.f / red[0];
    p[tid] = e0 * inv;
    p[tid + 256] = e1 * inv;
}

// ---------------- ctx: per (b,h) attn(512x512) @ V(512x64) -------------------
__global__ __launch_bounds__(256) void attn_ctx_kernel(
    const float* __restrict__ attn, const float* __restrict__ v,
    float* __restrict__ ctx)
{
    __shared__ float As[16][68];
    __shared__ float Vs[16][68];
    int bh = blockIdx.y;
    int b = bh / NHEADS, h = bh - b * NHEADS;
    int i0 = blockIdx.x * 64;
    int tid = threadIdx.x;
    int tx = tid & 15, ty = tid >> 4;
    float acc[4][4];
#pragma unroll
    for (int i = 0; i < 4; i++)
#pragma unroll
        for (int j = 0; j < 4; j++) acc[i][j] = 0.f;

    for (int k0 = 0; k0 < SEQ; k0 += 16) {
        {
            int ii = tid >> 2, kk4 = (tid & 3) * 4;
            float4 av = *(const float4*)(attn + ((size_t)bh * SEQ + i0 + ii) * SEQ + k0 + kk4);
            As[kk4 + 0][ii] = av.x; As[kk4 + 1][ii] = av.y;
            As[kk4 + 2][ii] = av.z; As[kk4 + 3][ii] = av.w;
            int kk = tid >> 4, d4 = (tid & 15) * 4;
            float4 vv = *(const float4*)(v + (size_t)(b * SEQ + k0 + kk) * Hdim + h * DHEAD + d4);
            *(float4*)&Vs[kk][d4] = vv;
        }
        __syncthreads();
#pragma unroll
        for (int kk = 0; kk < 16; kk++) {
            float4 a = *(const float4*)&As[kk][ty * 4];
            float4 bb = *(const float4*)&Vs[kk][tx * 4];
            float av[4] = {a.x, a.y, a.z, a.w};
            float bv[4] = {bb.x, bb.y, bb.z, bb.w};
#pragma unroll
            for (int i = 0; i < 4; i++)
#pragma unroll
                for (int j = 0; j < 4; j++)
                    acc[i][j] = fmaf(av[i], bv[j], acc[i][j]);
        }
        __syncthreads();
    }
#pragma unroll
    for (int i = 0; i < 4; i++) {
        int irow = b * SEQ + i0 + ty * 4 + i;
#pragma unroll
        for (int j = 0; j < 4; j++)
            ctx[(size_t)irow * Hdim + h * DHEAD + tx * 4 + j] = acc[i][j];
    }
}

// ---------------- heads: entity logits + pi/pj for relations ------------------
__global__ __launch_bounds__(256) void heads_kernel(
    const float* __restrict__ x, const float* __restrict__ W_ent,
    const float* __restrict__ b_ent, const float* __restrict__ W_rel,
    const float* __restrict__ b_rel, float* __restrict__ ent_out)
{
    int t = blockIdx.x;
    int tid = threadIdx.x;
    __shared__ float xs[Hdim];
    for (int i = tid; i < Hdim; i += 256) xs[i] = x[(size_t)t * Hdim + i];
    __syncthreads();
    int warp = tid >> 5, lane = tid & 31;
    for (int o = warp; o < NEnt + 2 * NRel; o += 8) {
        float s = 0.f;
        if (o < NEnt) {
            for (int k = lane; k < Hdim; k += 32) s += xs[k] * W_ent[(size_t)k * NEnt + o];
        } else if (o < NEnt + NRel) {
            int r = o - NEnt;
            for (int k = lane; k < Hdim; k += 32) s += xs[k] * W_rel[(size_t)k * NRel + r];
        } else {
            int r = o - NEnt - NRel;
            for (int k = lane; k < Hdim; k += 32) s += xs[k] * W_rel[(size_t)(Hdim + k) * NRel + r];
        }
#pragma unroll
        for (int off = 16; off; off >>= 1) s += __shfl_xor_sync(0xFFFFFFFFu, s, off);
        if (lane == 0) {
            if (o < NEnt)            ent_out[(size_t)t * NEnt + o] = s + b_ent[o];
            else if (o < NEnt + NRel) g_pi[t * NRel + (o - NEnt)] = s;
            else                      g_pj[t * NRel + (o - NEnt - NRel)] = s + b_rel[o - NEnt - NRel];
        }
    }
}

// ---------------- relation broadcast: rel[b,i,j,r] = pi[b,i,r] + pj[b,j,r] ----
__global__ __launch_bounds__(256) void relation_kernel(float* __restrict__ out)
{
    int bi = blockIdx.x;             // b*SEQ + i
    int b = bi >> 9;
    __shared__ float ps[NRel];
    if (threadIdx.x < NRel) ps[threadIdx.x] = g_pi[bi * NRel + threadIdx.x];
    __syncthreads();
    const float* pjb = g_pj + (size_t)(b << 9) * NRel;
    float* o = out + (size_t)bi * SEQ * NRel;
    for (int idx = threadIdx.x; idx < SEQ * NRel; idx += 256) {
        int r = idx % NRel;
        o[idx] = ps[r] + pjb[idx];
    }
}

// ---------------- host orchestration -----------------------------------------
extern "C" void kernel_launch(void* const* d_in, const int* in_sizes, int n_in,
                              void* d_out, int out_size)
{
    const int*   input_ids = (const int*)  d_in[0];
    const int*   attn_mask = (const int*)  d_in[1];
    const float* emb_word  = (const float*)d_in[2];
    const float* emb_pos   = (const float*)d_in[3];
    const float* emb_type  = (const float*)d_in[4];
    const float* emb_ln_g  = (const float*)d_in[5];
    const float* emb_ln_b  = (const float*)d_in[6];
    const float* Wq = (const float*)d_in[7];
    const float* bq = (const float*)d_in[8];
    const float* Wk = (const float*)d_in[9];
    const float* bk = (const float*)d_in[10];
    const float* Wv = (const float*)d_in[11];
    const float* bv = (const float*)d_in[12];
    const float* Wo = (const float*)d_in[13];
    const float* bo = (const float*)d_in[14];
    const float* ln1_g = (const float*)d_in[15];
    const float* ln1_b = (const float*)d_in[16];
    const float* W1 = (const float*)d_in[17];
    const float* b1 = (const float*)d_in[18];
    const float* W2 = (const float*)d_in[19];
    const float* b2 = (const float*)d_in[20];
    const float* ln2_g = (const float*)d_in[21];
    const float* ln2_b = (const float*)d_in[22];
    const float* W_ent = (const float*)d_in[23];
    const float* b_ent = (const float*)d_in[24];
    const float* W_rel = (const float*)d_in[25];
    const float* b_rel = (const float*)d_in[26];

    float *x, *q, *k, *v, *ctx, *ffn, *sc;
    cudaGetSymbolAddress((void**)&x,   g_x);
    cudaGetSymbolAddress((void**)&q,   g_q);
    cudaGetSymbolAddress((void**)&k,   g_k);
    cudaGetSymbolAddress((void**)&v,   g_v);
    cudaGetSymbolAddress((void**)&ctx, g_ctx);
    cudaGetSymbolAddress((void**)&ffn, g_ffn);
    cudaGetSymbolAddress((void**)&sc,  g_scores);

    embed_ln_kernel<<<MTOK, 256>>>(input_ids, emb_word, emb_pos, emb_type,
                                   emb_ln_g, emb_ln_b);
    abias_kernel<<<(BATCH * SEQ + 255) / 256, 256>>>(attn_mask);

    dim3 gH(Hdim / 64, MTOK / 128);     // N=768 projections
    dim3 gF1(FFdim / 64, MTOK / 128);   // N=3072
    dim3 gS(SEQ / 64, SEQ / 64, BATCH * NHEADS);
    dim3 gC(SEQ / 64, BATCH * NHEADS);

    for (int l = 0; l < NLAY; l++) {
        size_t wHH = (size_t)l * Hdim * Hdim;
        size_t wH  = (size_t)l * Hdim;
        sgemm_kernel<<<gH, 256>>>(x, Wq + wHH, bq + wH, q, MTOK, Hdim, Hdim, 0);
        sgemm_kernel<<<gH, 256>>>(x, Wk + wHH, bk + wH, k, MTOK, Hdim, Hdim, 0);
        sgemm_kernel<<<gH, 256>>>(x, Wv + wHH, bv + wH, v, MTOK, Hdim, Hdim, 0);
        attn_scores_kernel<<<gS, 256>>>(q, k);
        softmax_kernel<<<BATCH * NHEADS * SEQ, 256>>>(sc);
        attn_ctx_kernel<<<gC, 256>>>(sc, v, ctx);
        sgemm_kernel<<<gH, 256>>>(ctx, Wo + wHH, bo + wH, q, MTOK, Hdim, Hdim, 0);
        add_ln_kernel<<<MTOK, 256>>>(x, q, ln1_g + wH, ln1_b + wH);
        sgemm_kernel<<<gF1, 256>>>(x, W1 + (size_t)l * Hdim * FFdim, b1 + (size_t)l * FFdim,
                                   ffn, MTOK, FFdim, Hdim, 1);
        sgemm_kernel<<<gH, 256>>>(ffn, W2 + (size_t)l * FFdim * Hdim, b2 + wH,
                                  q, MTOK, Hdim, FFdim, 0);
        add_ln_kernel<<<MTOK, 256>>>(x, q, ln2_g + wH, ln2_b + wH);
    }

    float* out = (float*)d_out;
    heads_kernel<<<MTOK, 256>>>(x, W_ent, b_ent, W_rel, b_rel, out);
    relation_kernel<<<MTOK, 256>>>(out + (size_t)MTOK * NEnt);
}

// round 2
// speedup vs baseline: 1.0015x; 1.0015x over previous
#include <cuda_runtime.h>
#include <math.h>

#define Hdim   768
#define FFdim  3072
#define NLAY   12
#define NHEADS 12
#define DHEAD  64
#define BATCH  4
#define SEQ    512
#define MTOK   (BATCH*SEQ)   // 2048
#define NEnt   12
#define NRel   13

// ---------------- scratch (static device globals; no allocation) -------------
__device__ float g_x[MTOK*Hdim];
__device__ float g_q[MTOK*Hdim];
__device__ float g_k[MTOK*Hdim];
__device__ float g_v[MTOK*Hdim];
__device__ float g_ctx[MTOK*Hdim];
__device__ float g_ffn[MTOK*FFdim];
__device__ float g_scores[(size_t)BATCH*NHEADS*SEQ*SEQ];
__device__ float g_pi[MTOK*NRel];
__device__ float g_pj[MTOK*NRel];
__device__ float g_abias[BATCH*SEQ];

// ---------------- embedding + LayerNorm --------------------------------------
__global__ __launch_bounds__(256) void embed_ln_kernel(
    const int* __restrict__ ids, const float* __restrict__ ew,
    const float* __restrict__ ep, const float* __restrict__ et,
    const float* __restrict__ g, const float* __restrict__ b)
{
    int t = blockIdx.x;
    int s = t & (SEQ - 1);
    int id = ids[t];
    int tid = threadIdx.x;
    float vals[3];
    float sum = 0.f;
#pragma unroll
    for (int i = 0; i < 3; i++) {
        int c = tid + i * 256;
        vals[i] = ew[(size_t)id * Hdim + c] + ep[(size_t)s * Hdim + c] + et[c];
        sum += vals[i];
    }
    __shared__ float red[256];
    red[tid] = sum; __syncthreads();
    for (int o = 128; o; o >>= 1) { if (tid < o) red[tid] += red[tid + o]; __syncthreads(); }
    float mean = red[0] * (1.f / Hdim);
    __syncthreads();
    float sq = 0.f;
#pragma unroll
    for (int i = 0; i < 3; i++) { float d = vals[i] - mean; sq += d * d; }
    red[tid] = sq; __syncthreads();
    for (int o = 128; o; o >>= 1) { if (tid < o) red[tid] += red[tid + o]; __syncthreads(); }
    float rstd = rsqrtf(red[0] * (1.f / Hdim) + 1e-12f);
#pragma unroll
    for (int i = 0; i < 3; i++) {
        int c = tid + i * 256;
        g_x[(size_t)t * Hdim + c] = (vals[i] - mean) * rstd * g[c] + b[c];
    }
}

// ---------------- residual add + LayerNorm (in-place on x) -------------------
__global__ __launch_bounds__(256) void add_ln_kernel(
    float* __restrict__ x, const float* __restrict__ y,
    const float* __restrict__ g, const float* __restrict__ b)
{
    int t = blockIdx.x;
    int tid = threadIdx.x;
    float vals[3];
    float sum = 0.f;
#pragma unroll
    for (int i = 0; i < 3; i++) {
        int c = tid + i * 256;
        vals[i] = x[(size_t)t * Hdim + c] + y[(size_t)t * Hdim + c];
        sum += vals[i];
    }
    __shared__ float red[256];
    red[tid] = sum; __syncthreads();
    for (int o = 128; o; o >>= 1) { if (tid < o) red[tid] += red[tid + o]; __syncthreads(); }
    float mean = red[0] * (1.f / Hdim);
    __syncthreads();
    float sq = 0.f;
#pragma unroll
    for (int i = 0; i < 3; i++) { float d = vals[i] - mean; sq += d * d; }
    red[tid] = sq; __syncthreads();
    for (int o = 128; o; o >>= 1) { if (tid < o) red[tid] += red[tid + o]; __syncthreads(); }
    float rstd = rsqrtf(red[0] * (1.f / Hdim) + 1e-12f);
#pragma unroll
    for (int i = 0; i < 3; i++) {
        int c = tid + i * 256;
        x[(size_t)t * Hdim + c] = (vals[i] - mean) * rstd * g[c] + b[c];
    }
}

// ---------------- generic SGEMM: C = A(MxK) @ W(KxN) + bias [+ gelu] ---------
// BM=128, BN=64, BK=16, 256 threads, each thread 8x4 outputs.
__global__ __launch_bounds__(256) void sgemm_kernel(
    const float* __restrict__ A, const float* __restrict__ W,
    const float* __restrict__ bias, float* __restrict__ C,
    int M, int N, int K, int act)
{
    __shared__ float As[16][128];
    __shared__ float Bs[16][64];
    int tid = threadIdx.x;
    int tx = tid & 15;       // n dir
    int ty = tid >> 4;       // m dir
    int m0 = blockIdx.y * 128;
    int n0 = blockIdx.x * 64;

    float acc[8][4];
#pragma unroll
    for (int i = 0; i < 8; i++)
#pragma unroll
        for (int j = 0; j < 4; j++) acc[i][j] = 0.f;

    for (int k0 = 0; k0 < K; k0 += 16) {
        // A tile: 128x16 = 512 float4, 2 per thread; store transposed
#pragma unroll
        for (int u = 0; u < 2; u++) {
            int f = tid * 2 + u;          // 0..511
            int row = f >> 2;
            int kk4 = (f & 3) * 4;
            float4 av = *(const float4*)(A + (size_t)(m0 + row) * K + k0 + kk4);
            As[kk4 + 0][row] = av.x;
            As[kk4 + 1][row] = av.y;
            As[kk4 + 2][row] = av.z;
            As[kk4 + 3][row] = av.w;
        }
        // B tile: 16x64 = 256 float4, 1 per thread
        {
            int kk = tid >> 4;
            int nn = (tid & 15) * 4;
            *(float4*)(&Bs[kk][nn]) = *(const float4*)(W + (size_t)(k0 + kk) * N + n0 + nn);
        }
        __syncthreads();
#pragma unroll
        for (int kk = 0; kk < 16; kk++) {
            float4 a0 = *(const float4*)&As[kk][ty * 8];
            float4 a1 = *(const float4*)&As[kk][ty * 8 + 4];
            float4 b0 = *(const float4*)&Bs[kk][tx * 4];
            float a[8] = {a0.x, a0.y, a0.z, a0.w, a1.x, a1.y, a1.z, a1.w};
            float bb[4] = {b0.x, b0.y, b0.z, b0.w};
#pragma unroll
            for (int i = 0; i < 8; i++)
#pragma unroll
                for (int j = 0; j < 4; j++)
                    acc[i][j] = fmaf(a[i], bb[j], acc[i][j]);
        }
        __syncthreads();
    }
#pragma unroll
    for (int i = 0; i < 8; i++) {
        int row = m0 + ty * 8 + i;
#pragma unroll
        for (int j = 0; j < 4; j++) {
            int col = n0 + tx * 4 + j;
            float v = acc[i][j] + bias[col];
            if (act) v = 0.5f * v * (1.0f + erff(v * 0.70710678118654752f));
            C[(size_t)row * N + col] = v;
        }
    }
}

// ---------------- attention-mask bias -----------------------------------------
__global__ void abias_kernel(const int* __restrict__ mask)
{
    int i = blockIdx.x * blockDim.x + threadIdx.x;
    if (i < BATCH * SEQ) g_abias[i] = (1.f - (float)mask[i]) * -10000.f;
}

// ---------------- attention scores: per (b,h) Q(512x64) @ K^T ----------------
__global__ __launch_bounds__(256) void attn_scores_kernel(
    const float* __restrict__ q, const float* __restrict__ k)
{
    __shared__ float Qs[DHEAD][68];
    __shared__ float Ks[DHEAD][68];
    int bh = blockIdx.z;
    int b = bh / NHEADS, h = bh - b * NHEADS;
    int i0 = blockIdx.y * 64, j0 = blockIdx.x * 64;
    int tid = threadIdx.x;
#pragma unroll
    for (int u = 0; u < 4; u++) {
        int f = tid + u * 256;
        int r = f >> 4;
        int d4 = (f & 15) * 4;
        float4 qv = *(const float4*)(q + (size_t)(b * SEQ + i0 + r) * Hdim + h * DHEAD + d4);
        Qs[d4 + 0][r] = qv.x; Qs[d4 + 1][r] = qv.y; Qs[d4 + 2][r] = qv.z; Qs[d4 + 3][r] = qv.w;
        float4 kv = *(const float4*)(k + (size_t)(b * SEQ + j0 + r) * Hdim + h * DHEAD + d4);
        Ks[d4 + 0][r] = kv.x; Ks[d4 + 1][r] = kv.y; Ks[d4 + 2][r] = kv.z; Ks[d4 + 3][r] = kv.w;
    }
    __syncthreads();
    int tx = tid & 15, ty = tid >> 4;
    float acc[4][4];
#pragma unroll
    for (int i = 0; i < 4; i++)
#pragma unroll
        for (int j = 0; j < 4; j++) acc[i][j] = 0.f;
#pragma unroll
    for (int d = 0; d < DHEAD; d++) {
        float4 a = *(const float4*)&Qs[d][ty * 4];
        float4 bb = *(const float4*)&Ks[d][tx * 4];
        float av[4] = {a.x, a.y, a.z, a.w};
        float bv[4] = {bb.x, bb.y, bb.z, bb.w};
#pragma unroll
        for (int i = 0; i < 4; i++)
#pragma unroll
            for (int j = 0; j < 4; j++)
                acc[i][j] = fmaf(av[i], bv[j], acc[i][j]);
    }
#pragma unroll
    for (int i = 0; i < 4; i++) {
        int irow = i0 + ty * 4 + i;
#pragma unroll
        for (int j = 0; j < 4; j++) {
            int jcol = j0 + tx * 4 + j;
            g_scores[((size_t)bh * SEQ + irow) * SEQ + jcol] =
                acc[i][j] * 0.125f + g_abias[b * SEQ + jcol];
        }
    }
}

// ---------------- softmax over rows of 512 ------------------------------------
__global__ __launch_bounds__(256) void softmax_kernel(float* __restrict__ scores)
{
    float* p = scores + (size_t)blockIdx.x * SEQ;
    int tid = threadIdx.x;
    float a = p[tid], b = p[tid + 256];
    __shared__ float red[256];
    red[tid] = fmaxf(a, b); __syncthreads();
    for (int o = 128; o; o >>= 1) { if (tid < o) red[tid] = fmaxf(red[tid], red[tid + o]); __syncthreads(); }
    float m = red[0];
    __syncthreads();
    float e0 = expf(a - m), e1 = expf(b - m);
    red[tid] = e0 + e1; __syncthreads();
    for (int o = 128; o; o >>= 1) { if (tid < o) red[tid] += red[tid + o]; __syncthreads(); }
    float inv = 1.f / red[0];
    p[tid] = e0 * inv;
    p[tid + 256] = e1 * inv;
}

// ---------------- ctx: per (b,h) attn(512x512) @ V(512x64) -------------------
__global__ __launch_bounds__(256) void attn_ctx_kernel(
    const float* __restrict__ attn, const float* __restrict__ v,
    float* __restrict__ ctx)
{
    __shared__ float As[16][68];
    __shared__ float Vs[16][68];
    int bh = blockIdx.y;
    int b = bh / NHEADS, h = bh - b * NHEADS;
    int i0 = blockIdx.x * 64;
    int tid = threadIdx.x;
    int tx = tid & 15, ty = tid >> 4;
    float acc[4][4];
#pragma unroll
    for (int i = 0; i < 4; i++)
#pragma unroll
        for (int j = 0; j < 4; j++) acc[i][j] = 0.f;

    for (int k0 = 0; k0 < SEQ; k0 += 16) {
        {
            int ii = tid >> 2, kk4 = (tid & 3) * 4;
            float4 av = *(const float4*)(attn + ((size_t)bh * SEQ + i0 + ii) * SEQ + k0 + kk4);
            As[kk4 + 0][ii] = av.x; As[kk4 + 1][ii] = av.y;
            As[kk4 + 2][ii] = av.z; As[kk4 + 3][ii] = av.w;
            int kk = tid >> 4, d4 = (tid & 15) * 4;
            float4 vv = *(const float4*)(v + (size_t)(b * SEQ + k0 + kk) * Hdim + h * DHEAD + d4);
            *(float4*)&Vs[kk][d4] = vv;
        }
        __syncthreads();
#pragma unroll
        for (int kk = 0; kk < 16; kk++) {
            float4 a = *(const float4*)&As[kk][ty * 4];
            float4 bb = *(const float4*)&Vs[kk][tx * 4];
            float av[4] = {a.x, a.y, a.z, a.w};
            float bv[4] = {bb.x, bb.y, bb.z, bb.w};
#pragma unroll
            for (int i = 0; i < 4; i++)
#pragma unroll
                for (int j = 0; j < 4; j++)
                    acc[i][j] = fmaf(av[i], bv[j], acc[i][j]);
        }
        __syncthreads();
    }
#pragma unroll
    for (int i = 0; i < 4; i++) {
        int irow = b * SEQ + i0 + ty * 4 + i;
#pragma unroll
        for (int j = 0; j < 4; j++)
            ctx[(size_t)irow * Hdim + h * DHEAD + tx * 4 + j] = acc[i][j];
    }
}

// ---------------- heads: entity logits + pi/pj for relations ------------------
__global__ __launch_bounds__(256) void heads_kernel(
    const float* __restrict__ x, const float* __restrict__ W_ent,
    const float* __restrict__ b_ent, const float* __restrict__ W_rel,
    const float* __restrict__ b_rel, float* __restrict__ ent_out)
{
    int t = blockIdx.x;
    int tid = threadIdx.x;
    __shared__ float xs[Hdim];
    for (int i = tid; i < Hdim; i += 256) xs[i] = x[(size_t)t * Hdim + i];
    __syncthreads();
    int warp = tid >> 5, lane = tid & 31;
    for (int o = warp; o < NEnt + 2 * NRel; o += 8) {
        float s = 0.f;
        if (o < NEnt) {
            for (int k = lane; k < Hdim; k += 32) s += xs[k] * W_ent[(size_t)k * NEnt + o];
        } else if (o < NEnt + NRel) {
            int r = o - NEnt;
            for (int k = lane; k < Hdim; k += 32) s += xs[k] * W_rel[(size_t)k * NRel + r];
        } else {
            int r = o - NEnt - NRel;
            for (int k = lane; k < Hdim; k += 32) s += xs[k] * W_rel[(size_t)(Hdim + k) * NRel + r];
        }
#pragma unroll
        for (int off = 16; off; off >>= 1) s += __shfl_xor_sync(0xFFFFFFFFu, s, off);
        if (lane == 0) {
            if (o < NEnt)            ent_out[(size_t)t * NEnt + o] = s + b_ent[o];
            else if (o < NEnt + NRel) g_pi[t * NRel + (o - NEnt)] = s;
            else                      g_pj[t * NRel + (o - NEnt - NRel)] = s + b_rel[o - NEnt - NRel];
        }
    }
}

// ---------------- relation broadcast: rel[b,i,j,r] = pi[b,i,r] + pj[b,j,r] ----
__global__ __launch_bounds__(256) void relation_kernel(float* __restrict__ out)
{
    int bi = blockIdx.x;             // b*SEQ + i
    int b = bi >> 9;
    __shared__ float ps[NRel];
    if (threadIdx.x < NRel) ps[threadIdx.x] = g_pi[bi * NRel + threadIdx.x];
    __syncthreads();
    const float* pjb = g_pj + (size_t)(b << 9) * NRel;
    float* o = out + (size_t)bi * SEQ * NRel;
    for (int idx = threadIdx.x; idx < SEQ * NRel; idx += 256) {
        int r = idx % NRel;
        o[idx] = ps[r] + pjb[idx];
    }
}

// ---------------- host orchestration -----------------------------------------
extern "C" void kernel_launch(void* const* d_in, const int* in_sizes, int n_in,
                              void* d_out, int out_size)
{
    const int*   input_ids = (const int*)  d_in[0];
    const int*   attn_mask = (const int*)  d_in[1];
    const float* emb_word  = (const float*)d_in[2];
    const float* emb_pos   = (const float*)d_in[3];
    const float* emb_type  = (const float*)d_in[4];
    const float* emb_ln_g  = (const float*)d_in[5];
    const float* emb_ln_b  = (const float*)d_in[6];
    const float* Wq = (const float*)d_in[7];
    const float* bq = (const float*)d_in[8];
    const float* Wk = (const float*)d_in[9];
    const float* bk = (const float*)d_in[10];
    const float* Wv = (const float*)d_in[11];
    const float* bv = (const float*)d_in[12];
    const float* Wo = (const float*)d_in[13];
    const float* bo = (const float*)d_in[14];
    const float* ln1_g = (const float*)d_in[15];
    const float* ln1_b = (const float*)d_in[16];
    const float* W1 = (const float*)d_in[17];
    const float* b1 = (const float*)d_in[18];
    const float* W2 = (const float*)d_in[19];
    const float* b2 = (const float*)d_in[20];
    const float* ln2_g = (const float*)d_in[21];
    const float* ln2_b = (const float*)d_in[22];
    const float* W_ent = (const float*)d_in[23];
    const float* b_ent = (const float*)d_in[24];
    const float* W_rel = (const float*)d_in[25];
    const float* b_rel = (const float*)d_in[26];

    float *x, *q, *k, *v, *ctx, *ffn, *sc;
    cudaGetSymbolAddress((void**)&x,   g_x);
    cudaGetSymbolAddress((void**)&q,   g_q);
    cudaGetSymbolAddress((void**)&k,   g_k);
    cudaGetSymbolAddress((void**)&v,   g_v);
    cudaGetSymbolAddress((void**)&ctx, g_ctx);
    cudaGetSymbolAddress((void**)&ffn, g_ffn);
    cudaGetSymbolAddress((void**)&sc,  g_scores);

    embed_ln_kernel<<<MTOK, 256>>>(input_ids, emb_word, emb_pos, emb_type,
                                   emb_ln_g, emb_ln_b);
    abias_kernel<<<(BATCH * SEQ + 255) / 256, 256>>>(attn_mask);

    dim3 gH(Hdim / 64, MTOK / 128);     // N=768 projections
    dim3 gF1(FFdim / 64, MTOK / 128);   // N=3072
    dim3 gS(SEQ / 64, SEQ / 64, BATCH * NHEADS);
    dim3 gC(SEQ / 64, BATCH * NHEADS);

    for (int l = 0; l < NLAY; l++) {
        size_t wHH = (size_t)l * Hdim * Hdim;
        size_t wH  = (size_t)l * Hdim;
        sgemm_kernel<<<gH, 256>>>(x, Wq + wHH, bq + wH, q, MTOK, Hdim, Hdim, 0);
        sgemm_kernel<<<gH, 256>>>(x, Wk + wHH, bk + wH, k, MTOK, Hdim, Hdim, 0);
        sgemm_kernel<<<gH, 256>>>(x, Wv + wHH, bv + wH, v, MTOK, Hdim, Hdim, 0);
        attn_scores_kernel<<<gS, 256>>>(q, k);
        softmax_kernel<<<BATCH * NHEADS * SEQ, 256>>>(sc);
        attn_ctx_kernel<<<gC, 256>>>(sc, v, ctx);
        sgemm_kernel<<<gH, 256>>>(ctx, Wo + wHH, bo + wH, q, MTOK, Hdim, Hdim, 0);
        add_ln_kernel<<<MTOK, 256>>>(x, q, ln1_g + wH, ln1_b + wH);
        sgemm_kernel<<<gF1, 256>>>(x, W1 + (size_t)l * Hdim * FFdim, b1 + (size_t)l * FFdim,
                                   ffn, MTOK, FFdim, Hdim, 1);
        sgemm_kernel<<<gH, 256>>>(ffn, W2 + (size_t)l * FFdim * Hdim, b2 + wH,
                                  q, MTOK, Hdim, FFdim, 0);
        add_ln_kernel<<<MTOK, 256>>>(x, q, ln2_g + wH, ln2_b + wH);
    }

    float* out = (float*)d_out;
    heads_kernel<<<MTOK, 256>>>(x, W_ent, b_ent, W_rel, b_rel, out);
    relation_kernel<<<MTOK, 256>>>(out + (size_t)MTOK * NEnt);
}

// round 3
// speedup vs baseline: 1.9886x; 1.9855x over previous
#include <cuda_runtime.h>
#include <math.h>

#define Hdim   768
#define FFdim  3072
#define NLAY   12
#define NHEADS 12
#define DHEAD  64
#define BATCH  4
#define SEQ    512
#define MTOK   (BATCH*SEQ)   // 2048
#define NEnt   12
#define NRel   13

// ---------------- scratch (static device globals; no allocation) -------------
__device__ float g_x[MTOK*Hdim];
__device__ float g_q[MTOK*Hdim];
__device__ float g_k[MTOK*Hdim];
__device__ float g_v[MTOK*Hdim];
__device__ float g_ctx[MTOK*Hdim];
__device__ float g_ffn[MTOK*FFdim];
__device__ float g_scores[(size_t)BATCH*NHEADS*SEQ*SEQ];
__device__ float g_pi[MTOK*NRel];
__device__ float g_pj[MTOK*NRel];
__device__ float g_abias[BATCH*SEQ];

// ---------------- tf32 mma helpers -------------------------------------------
__device__ __forceinline__ unsigned f2tf(float f) {
    unsigned u;
    asm("cvt.rna.tf32.f32 %0, %1;" : "=r"(u) : "f"(f));
    return u;
}
__device__ __forceinline__ void mma8(float* c, unsigned a0, unsigned a1,
                                     unsigned a2, unsigned a3,
                                     unsigned b0, unsigned b1) {
    asm volatile(
        "mma.sync.aligned.m16n8k8.row.col.f32.tf32.tf32.f32 "
        "{%0,%1,%2,%3},{%4,%5,%6,%7},{%8,%9},{%0,%1,%2,%3};"
        : "+f"(c[0]), "+f"(c[1]), "+f"(c[2]), "+f"(c[3])
        : "r"(a0), "r"(a1), "r"(a2), "r"(a3), "r"(b0), "r"(b1));
}
#define CPA16(dst, src) \
    asm volatile("cp.async.ca.shared.global [%0], [%1], 16;" :: "r"(dst), "l"(src))
__device__ __forceinline__ void cp_commit() { asm volatile("cp.async.commit_group;"); }
__device__ __forceinline__ void cp_wait1()  { asm volatile("cp.async.wait_group 1;"); }

// ---------------- embedding + LayerNorm --------------------------------------
__global__ __launch_bounds__(256) void embed_ln_kernel(
    const int* __restrict__ ids, const float* __restrict__ ew,
    const float* __restrict__ ep, const float* __restrict__ et,
    const float* __restrict__ g, const float* __restrict__ b)
{
    int t = blockIdx.x;
    int s = t & (SEQ - 1);
    int id = ids[t];
    int tid = threadIdx.x;
    float vals[3];
    float sum = 0.f;
#pragma unroll
    for (int i = 0; i < 3; i++) {
        int c = tid + i * 256;
        vals[i] = ew[(size_t)id * Hdim + c] + ep[(size_t)s * Hdim + c] + et[c];
        sum += vals[i];
    }
    __shared__ float red[256];
    red[tid] = sum; __syncthreads();
    for (int o = 128; o; o >>= 1) { if (tid < o) red[tid] += red[tid + o]; __syncthreads(); }
    float mean = red[0] * (1.f / Hdim);
    __syncthreads();
    float sq = 0.f;
#pragma unroll
    for (int i = 0; i < 3; i++) { float d = vals[i] - mean; sq += d * d; }
    red[tid] = sq; __syncthreads();
    for (int o = 128; o; o >>= 1) { if (tid < o) red[tid] += red[tid + o]; __syncthreads(); }
    float rstd = rsqrtf(red[0] * (1.f / Hdim) + 1e-12f);
#pragma unroll
    for (int i = 0; i < 3; i++) {
        int c = tid + i * 256;
        g_x[(size_t)t * Hdim + c] = (vals[i] - mean) * rstd * g[c] + b[c];
    }
}

// ---------------- residual add + LayerNorm (in-place on x) -------------------
__global__ __launch_bounds__(256) void add_ln_kernel(
    float* __restrict__ x, const float* __restrict__ y,
    const float* __restrict__ g, const float* __restrict__ b)
{
    int t = blockIdx.x;
    int tid = threadIdx.x;
    float vals[3];
    float sum = 0.f;
#pragma unroll
    for (int i = 0; i < 3; i++) {
        int c = tid + i * 256;
        vals[i] = x[(size_t)t * Hdim + c] + y[(size_t)t * Hdim + c];
        sum += vals[i];
    }
    __shared__ float red[256];
    red[tid] = sum; __syncthreads();
    for (int o = 128; o; o >>= 1) { if (tid < o) red[tid] += red[tid + o]; __syncthreads(); }
    float mean = red[0] * (1.f / Hdim);
    __syncthreads();
    float sq = 0.f;
#pragma unroll
    for (int i = 0; i < 3; i++) { float d = vals[i] - mean; sq += d * d; }
    red[tid] = sq; __syncthreads();
    for (int o = 128; o; o >>= 1) { if (tid < o) red[tid] += red[tid + o]; __syncthreads(); }
    float rstd = rsqrtf(red[0] * (1.f / Hdim) + 1e-12f);
#pragma unroll
    for (int i = 0; i < 3; i++) {
        int c = tid + i * 256;
        x[(size_t)t * Hdim + c] = (vals[i] - mean) * rstd * g[c] + b[c];
    }
}

// ---------------- tf32 GEMM: C = A(MxK) @ W(KxN) + bias [+gelu] --------------
// BM=128, BN=64, BK=16. 128 threads = 4 warps (2x2), warp tile 64x32.
// blockIdx.z picks among up to 3 (W, bias, C) triples (fused QKV).
__global__ __launch_bounds__(128) void tf32_gemm_kernel(
    const float* __restrict__ A,
    const float* __restrict__ W0, const float* __restrict__ W1, const float* __restrict__ W2,
    const float* __restrict__ bias0, const float* __restrict__ bias1, const float* __restrict__ bias2,
    float* __restrict__ C0, float* __restrict__ C1, float* __restrict__ C2,
    int M, int N, int K, int act)
{
    int z = blockIdx.z;
    const float* W    = (z == 0) ? W0    : (z == 1) ? W1    : W2;
    const float* bias = (z == 0) ? bias0 : (z == 1) ? bias1 : bias2;
    float*       C    = (z == 0) ? C0    : (z == 1) ? C1    : C2;

    __shared__ float As[2][128][20];  // [m][k], pad 20 -> conflict-free frags
    __shared__ float Bs[2][16][72];   // [k][n], pad 72 -> conflict-free frags

    int tid = threadIdx.x;
    int warp = tid >> 5, lane = tid & 31;
    int r = lane >> 2, cq = lane & 3;
    int wm = (warp >> 1) * 64, wn = (warp & 1) * 32;
    int m0 = blockIdx.y * 128, n0 = blockIdx.x * 64;

    float acc[4][4][4];
#pragma unroll
    for (int i = 0; i < 4; i++)
#pragma unroll
        for (int j = 0; j < 4; j++)
#pragma unroll
            for (int t = 0; t < 4; t++) acc[i][j][t] = 0.f;

    int KT = K / 16;

    // prologue load
    {
        const float* a = A + (size_t)(m0 + tid) * K;
        unsigned da = (unsigned)__cvta_generic_to_shared(&As[0][tid][0]);
        CPA16(da, a); CPA16(da + 16, a + 4); CPA16(da + 32, a + 8); CPA16(da + 48, a + 12);
#pragma unroll
        for (int u = 0; u < 2; u++) {
            int c = tid + u * 128;
            int row = c >> 4, off = (c & 15) << 2;
            unsigned db = (unsigned)__cvta_generic_to_shared(&Bs[0][row][off]);
            CPA16(db, W + (size_t)row * N + n0 + off);
        }
        cp_commit();
    }

    for (int kt = 0; kt < KT; kt++) {
        int cur = kt & 1;
        if (kt + 1 < KT) {
            int k0 = (kt + 1) * 16;
            const float* a = A + (size_t)(m0 + tid) * K + k0;
            unsigned da = (unsigned)__cvta_generic_to_shared(&As[cur ^ 1][tid][0]);
            CPA16(da, a); CPA16(da + 16, a + 4); CPA16(da + 32, a + 8); CPA16(da + 48, a + 12);
#pragma unroll
            for (int u = 0; u < 2; u++) {
                int c = tid + u * 128;
                int row = c >> 4, off = (c & 15) << 2;
                unsigned db = (unsigned)__cvta_generic_to_shared(&Bs[cur ^ 1][row][off]);
                CPA16(db, W + (size_t)(k0 + row) * N + n0 + off);
            }
        }
        cp_commit();
        cp_wait1();
        __syncthreads();

#pragma unroll
        for (int ks = 0; ks < 2; ks++) {
            int kk = ks * 8;
            unsigned af[4][4], bf[4][2];
#pragma unroll
            for (int mt = 0; mt < 4; mt++) {
                int mr = wm + mt * 16 + r;
                af[mt][0] = f2tf(As[cur][mr    ][kk + cq]);
                af[mt][1] = f2tf(As[cur][mr + 8][kk + cq]);
                af[mt][2] = f2tf(As[cur][mr    ][kk + cq + 4]);
                af[mt][3] = f2tf(As[cur][mr + 8][kk + cq + 4]);
            }
#pragma unroll
            for (int nt = 0; nt < 4; nt++) {
                int nn = wn + nt * 8 + r;
                bf[nt][0] = f2tf(Bs[cur][kk + cq    ][nn]);
                bf[nt][1] = f2tf(Bs[cur][kk + cq + 4][nn]);
            }
#pragma unroll
            for (int mt = 0; mt < 4; mt++)
#pragma unroll
                for (int nt = 0; nt < 4; nt++)
                    mma8(acc[mt][nt], af[mt][0], af[mt][1], af[mt][2], af[mt][3],
                         bf[nt][0], bf[nt][1]);
        }
        __syncthreads();
    }

    // epilogue
#pragma unroll
    for (int mt = 0; mt < 4; mt++) {
        int row = m0 + wm + mt * 16 + r;
#pragma unroll
        for (int nt = 0; nt < 4; nt++) {
            int col = n0 + wn + nt * 8 + cq * 2;
            float2 bb = *(const float2*)&bias[col];
            float v0 = acc[mt][nt][0] + bb.x;
            float v1 = acc[mt][nt][1] + bb.y;
            float v2 = acc[mt][nt][2] + bb.x;
            float v3 = acc[mt][nt][3] + bb.y;
            if (act) {
                v0 = 0.5f * v0 * (1.0f + erff(v0 * 0.70710678118654752f));
                v1 = 0.5f * v1 * (1.0f + erff(v1 * 0.70710678118654752f));
                v2 = 0.5f * v2 * (1.0f + erff(v2 * 0.70710678118654752f));
                v3 = 0.5f * v3 * (1.0f + erff(v3 * 0.70710678118654752f));
            }
            *(float2*)&C[(size_t)row * N + col]       = make_float2(v0, v1);
            *(float2*)&C[(size_t)(row + 8) * N + col] = make_float2(v2, v3);
        }
    }
}

// ---------------- attention-mask bias -----------------------------------------
__global__ void abias_kernel(const int* __restrict__ mask)
{
    int i = blockIdx.x * blockDim.x + threadIdx.x;
    if (i < BATCH * SEQ) g_abias[i] = (1.f - (float)mask[i]) * -10000.f;
}

// ---------------- attention scores (tf32): per (b,h) Q(512x64) @ K^T ----------
// Block 128 thr, 64x64 tile, K=64 resident. Warp tile 32x32 (warps 2x2).
__global__ __launch_bounds__(128) void attn_scores_tf32(
    const float* __restrict__ q, const float* __restrict__ k)
{
    __shared__ float Qs[64][68];  // [i][d]
    __shared__ float Ks[64][68];  // [j][d]
    int bh = blockIdx.z;
    int b = bh / NHEADS, h = bh - b * NHEADS;
    int i0 = blockIdx.y * 64, j0 = blockIdx.x * 64;
    int tid = threadIdx.x;

#pragma unroll
    for (int u = 0; u < 8; u++) {
        int c = tid + u * 128;
        int row = c >> 4, off = (c & 15) << 2;
        *(float4*)&Qs[row][off] =
            *(const float4*)(q + (size_t)(b * SEQ + i0 + row) * Hdim + h * DHEAD + off);
        *(float4*)&Ks[row][off] =
            *(const float4*)(k + (size_t)(b * SEQ + j0 + row) * Hdim + h * DHEAD + off);
    }
    __syncthreads();

    int warp = tid >> 5, lane = tid & 31;
    int r = lane >> 2, cq = lane & 3;
    int wm = (warp >> 1) * 32, wn = (warp & 1) * 32;

    float acc[2][4][4];
#pragma unroll
    for (int i = 0; i < 2; i++)
#pragma unroll
        for (int j = 0; j < 4; j++)
#pragma unroll
            for (int t = 0; t < 4; t++) acc[i][j][t] = 0.f;

#pragma unroll
    for (int ks = 0; ks < 8; ks++) {
        int kk = ks * 8;
        unsigned af[2][4], bf[4][2];
#pragma unroll
        for (int mt = 0; mt < 2; mt++) {
            int mr = wm + mt * 16 + r;
            af[mt][0] = f2tf(Qs[mr    ][kk + cq]);
            af[mt][1] = f2tf(Qs[mr + 8][kk + cq]);
            af[mt][2] = f2tf(Qs[mr    ][kk + cq + 4]);
            af[mt][3] = f2tf(Qs[mr + 8][kk + cq + 4]);
        }
#pragma unroll
        for (int nt = 0; nt < 4; nt++) {
            int nn = wn + nt * 8 + r;
            bf[nt][0] = f2tf(Ks[nn][kk + cq]);
            bf[nt][1] = f2tf(Ks[nn][kk + cq + 4]);
        }
#pragma unroll
        for (int mt = 0; mt < 2; mt++)
#pragma unroll
            for (int nt = 0; nt < 4; nt++)
                mma8(acc[mt][nt], af[mt][0], af[mt][1], af[mt][2], af[mt][3],
                     bf[nt][0], bf[nt][1]);
    }

#pragma unroll
    for (int mt = 0; mt < 2; mt++) {
        int irow = i0 + wm + mt * 16 + r;
#pragma unroll
        for (int nt = 0; nt < 4; nt++) {
            int jcol = j0 + wn + nt * 8 + cq * 2;
            float2 ab = *(const float2*)&g_abias[b * SEQ + jcol];
            float* o0 = &g_scores[((size_t)bh * SEQ + irow) * SEQ + jcol];
            float* o1 = &g_scores[((size_t)bh * SEQ + irow + 8) * SEQ + jcol];
            *(float2*)o0 = make_float2(acc[mt][nt][0] * 0.125f + ab.x,
                                       acc[mt][nt][1] * 0.125f + ab.y);
            *(float2*)o1 = make_float2(acc[mt][nt][2] * 0.125f + ab.x,
                                       acc[mt][nt][3] * 0.125f + ab.y);
        }
    }
}

// ---------------- softmax over rows of 512 ------------------------------------
__global__ __launch_bounds__(256) void softmax_kernel(float* __restrict__ scores)
{
    float* p = scores + (size_t)blockIdx.x * SEQ;
    int tid = threadIdx.x;
    float a = p[tid], b = p[tid + 256];
    __shared__ float red[256];
    red[tid] = fmaxf(a, b); __syncthreads();
    for (int o = 128; o; o >>= 1) { if (tid < o) red[tid] = fmaxf(red[tid], red[tid + o]); __syncthreads(); }
    float m = red[0];
    __syncthreads();
    float e0 = expf(a - m), e1 = expf(b - m);
    red[tid] = e0 + e1; __syncthreads();
    for (int o = 128; o; o >>= 1) { if (tid < o) red[tid] += red[tid + o]; __syncthreads(); }
    float inv = 1.f / red[0];
    p[tid] = e0 * inv;
    p[tid + 256] = e1 * inv;
}

// ---------------- ctx (tf32): per (b,h) attn(512x512) @ V(512x64) -------------
// BM=128, BN=64(=DH), BK=16. 128 thr, warp tile 64x32.
__global__ __launch_bounds__(128) void attn_ctx_tf32(
    const float* __restrict__ attn, const float* __restrict__ v,
    float* __restrict__ ctx)
{
    __shared__ float As[2][128][20];
    __shared__ float Bs[2][16][72];
    int bh = blockIdx.y;
    int b = bh / NHEADS, h = bh - b * NHEADS;
    int m0 = blockIdx.x * 128;
    const float* A = attn + (size_t)bh * SEQ * SEQ;
    const float* V = v + (size_t)b * SEQ * Hdim + h * DHEAD;

    int tid = threadIdx.x;
    int warp = tid >> 5, lane = tid & 31;
    int r = lane >> 2, cq = lane & 3;
    int wm = (warp >> 1) * 64, wn = (warp & 1) * 32;

    float acc[4][4][4];
#pragma unroll
    for (int i = 0; i < 4; i++)
#pragma unroll
        for (int j = 0; j < 4; j++)
#pragma unroll
            for (int t = 0; t < 4; t++) acc[i][j][t] = 0.f;

    {
        const float* a = A + (size_t)(m0 + tid) * SEQ;
        unsigned da = (unsigned)__cvta_generic_to_shared(&As[0][tid][0]);
        CPA16(da, a); CPA16(da + 16, a + 4); CPA16(da + 32, a + 8); CPA16(da + 48, a + 12);
#pragma unroll
        for (int u = 0; u < 2; u++) {
            int c = tid + u * 128;
            int row = c >> 4, off = (c & 15) << 2;
            unsigned db = (unsigned)__cvta_generic_to_shared(&Bs[0][row][off]);
            CPA16(db, V + (size_t)row * Hdim + off);
        }
        cp_commit();
    }

    const int KT = SEQ / 16;
    for (int kt = 0; kt < KT; kt++) {
        int cur = kt & 1;
        if (kt + 1 < KT) {
            int k0 = (kt + 1) * 16;
            const float* a = A + (size_t)(m0 + tid) * SEQ + k0;
            unsigned da = (unsigned)__cvta_generic_to_shared(&As[cur ^ 1][tid][0]);
            CPA16(da, a); CPA16(da + 16, a + 4); CPA16(da + 32, a + 8); CPA16(da + 48, a + 12);
#pragma unroll
            for (int u = 0; u < 2; u++) {
                int c = tid + u * 128;
                int row = c >> 4, off = (c & 15) << 2;
                unsigned db = (unsigned)__cvta_generic_to_shared(&Bs[cur ^ 1][row][off]);
                CPA16(db, V + (size_t)(k0 + row) * Hdim + off);
            }
        }
        cp_commit();
        cp_wait1();
        __syncthreads();

#pragma unroll
        for (int ks = 0; ks < 2; ks++) {
            int kk = ks * 8;
            unsigned af[4][4], bf[4][2];
#pragma unroll
            for (int mt = 0; mt < 4; mt++) {
                int mr = wm + mt * 16 + r;
                af[mt][0] = f2tf(As[cur][mr    ][kk + cq]);
                af[mt][1] = f2tf(As[cur][mr + 8][kk + cq]);
                af[mt][2] = f2tf(As[cur][mr    ][kk + cq + 4]);
                af[mt][3] = f2tf(As[cur][mr + 8][kk + cq + 4]);
            }
#pragma unroll
            for (int nt = 0; nt < 4; nt++) {
                int nn = wn + nt * 8 + r;
                bf[nt][0] = f2tf(Bs[cur][kk + cq    ][nn]);
                bf[nt][1] = f2tf(Bs[cur][kk + cq + 4][nn]);
            }
#pragma unroll
            for (int mt = 0; mt < 4; mt++)
#pragma unroll
                for (int nt = 0; nt < 4; nt++)
                    mma8(acc[mt][nt], af[mt][0], af[mt][1], af[mt][2], af[mt][3],
                         bf[nt][0], bf[nt][1]);
        }
        __syncthreads();
    }

#pragma unroll
    for (int mt = 0; mt < 4; mt++) {
        int irow = b * SEQ + m0 + wm + mt * 16 + r;
#pragma unroll
        for (int nt = 0; nt < 4; nt++) {
            int col = h * DHEAD + wn + nt * 8 + cq * 2;
            *(float2*)&ctx[(size_t)irow * Hdim + col] =
                make_float2(acc[mt][nt][0], acc[mt][nt][1]);
            *(float2*)&ctx[(size_t)(irow + 8) * Hdim + col] =
                make_float2(acc[mt][nt][2], acc[mt][nt][3]);
        }
    }
}

// ---------------- heads: entity logits + pi/pj for relations ------------------
__global__ __launch_bounds__(256) void heads_kernel(
    const float* __restrict__ x, const float* __restrict__ W_ent,
    const float* __restrict__ b_ent, const float* __restrict__ W_rel,
    const float* __restrict__ b_rel, float* __restrict__ ent_out)
{
    int t = blockIdx.x;
    int tid = threadIdx.x;
    __shared__ float xs[Hdim];
    for (int i = tid; i < Hdim; i += 256) xs[i] = x[(size_t)t * Hdim + i];
    __syncthreads();
    int warp = tid >> 5, lane = tid & 31;
    for (int o = warp; o < NEnt + 2 * NRel; o += 8) {
        float s = 0.f;
        if (o < NEnt) {
            for (int k = lane; k < Hdim; k += 32) s += xs[k] * W_ent[(size_t)k * NEnt + o];
        } else if (o < NEnt + NRel) {
            int rr = o - NEnt;
            for (int k = lane; k < Hdim; k += 32) s += xs[k] * W_rel[(size_t)k * NRel + rr];
        } else {
            int rr = o - NEnt - NRel;
            for (int k = lane; k < Hdim; k += 32) s += xs[k] * W_rel[(size_t)(Hdim + k) * NRel + rr];
        }
#pragma unroll
        for (int off = 16; off; off >>= 1) s += __shfl_xor_sync(0xFFFFFFFFu, s, off);
        if (lane == 0) {
            if (o < NEnt)             ent_out[(size_t)t * NEnt + o] = s + b_ent[o];
            else if (o < NEnt + NRel) g_pi[t * NRel + (o - NEnt)] = s;
            else                      g_pj[t * NRel + (o - NEnt - NRel)] = s + b_rel[o - NEnt - NRel];
        }
    }
}

// ---------------- relation broadcast: rel[b,i,j,r] = pi[b,i,r] + pj[b,j,r] ----
__global__ __launch_bounds__(256) void relation_kernel(float* __restrict__ out)
{
    int bi = blockIdx.x;
    int b = bi >> 9;
    __shared__ float ps[NRel];
    if (threadIdx.x < NRel) ps[threadIdx.x] = g_pi[bi * NRel + threadIdx.x];
    __syncthreads();
    const float* pjb = g_pj + (size_t)(b << 9) * NRel;
    float* o = out + (size_t)bi * SEQ * NRel;
    for (int idx = threadIdx.x; idx < SEQ * NRel; idx += 256) {
        int r = idx % NRel;
        o[idx] = ps[r] + pjb[idx];
    }
}

// ---------------- host orchestration -----------------------------------------
extern "C" void kernel_launch(void* const* d_in, const int* in_sizes, int n_in,
                              void* d_out, int out_size)
{
    const int*   input_ids = (const int*)  d_in[0];
    const int*   attn_mask = (const int*)  d_in[1];
    const float* emb_word  = (const float*)d_in[2];
    const float* emb_pos   = (const float*)d_in[3];
    const float* emb_type  = (const float*)d_in[4];
    const float* emb_ln_g  = (const float*)d_in[5];
    const float* emb_ln_b  = (const float*)d_in[6];
    const float* Wq = (const float*)d_in[7];
    const float* bq = (const float*)d_in[8];
    const float* Wk = (const float*)d_in[9];
    const float* bk = (const float*)d_in[10];
    const float* Wv = (const float*)d_in[11];
    const float* bv = (const float*)d_in[12];
    const float* Wo = (const float*)d_in[13];
    const float* bo = (const float*)d_in[14];
    const float* ln1_g = (const float*)d_in[15];
    const float* ln1_b = (const float*)d_in[16];
    const float* W1 = (const float*)d_in[17];
    const float* b1 = (const float*)d_in[18];
    const float* W2 = (const float*)d_in[19];
    const float* b2 = (const float*)d_in[20];
    const float* ln2_g = (const float*)d_in[21];
    const float* ln2_b = (const float*)d_in[22];
    const float* W_ent = (const float*)d_in[23];
    const float* b_ent = (const float*)d_in[24];
    const float* W_rel = (const float*)d_in[25];
    const float* b_rel = (const float*)d_in[26];

    float *x, *q, *k, *v, *ctx, *ffn, *sc;
    cudaGetSymbolAddress((void**)&x,   g_x);
    cudaGetSymbolAddress((void**)&q,   g_q);
    cudaGetSymbolAddress((void**)&k,   g_k);
    cudaGetSymbolAddress((void**)&v,   g_v);
    cudaGetSymbolAddress((void**)&ctx, g_ctx);
    cudaGetSymbolAddress((void**)&ffn, g_ffn);
    cudaGetSymbolAddress((void**)&sc,  g_scores);

    embed_ln_kernel<<<MTOK, 256>>>(input_ids, emb_word, emb_pos, emb_type,
                                   emb_ln_g, emb_ln_b);
    abias_kernel<<<(BATCH * SEQ + 255) / 256, 256>>>(attn_mask);

    dim3 gQKV(Hdim / 64, MTOK / 128, 3);
    dim3 gH(Hdim / 64, MTOK / 128, 1);
    dim3 gF1(FFdim / 64, MTOK / 128, 1);
    dim3 gS(SEQ / 64, SEQ / 64, BATCH * NHEADS);
    dim3 gC(SEQ / 128, BATCH * NHEADS);

    for (int l = 0; l < NLAY; l++) {
        size_t wHH = (size_t)l * Hdim * Hdim;
        size_t wH  = (size_t)l * Hdim;
        tf32_gemm_kernel<<<gQKV, 128>>>(x, Wq + wHH, Wk + wHH, Wv + wHH,
                                        bq + wH, bk + wH, bv + wH,
                                        q, k, v, MTOK, Hdim, Hdim, 0);
        attn_scores_tf32<<<gS, 128>>>(q, k);
        softmax_kernel<<<BATCH * NHEADS * SEQ, 256>>>(sc);
        attn_ctx_tf32<<<gC, 128>>>(sc, v, ctx);
        tf32_gemm_kernel<<<gH, 128>>>(ctx, Wo + wHH, Wo + wHH, Wo + wHH,
                                      bo + wH, bo + wH, bo + wH,
                                      q, q, q, MTOK, Hdim, Hdim, 0);
        add_ln_kernel<<<MTOK, 256>>>(x, q, ln1_g + wH, ln1_b + wH);
        tf32_gemm_kernel<<<gF1, 128>>>(x,
                                       W1 + (size_t)l * Hdim * FFdim, W1 + (size_t)l * Hdim * FFdim, W1 + (size_t)l * Hdim * FFdim,
                                       b1 + (size_t)l * FFdim, b1 + (size_t)l * FFdim, b1 + (size_t)l * FFdim,
                                       ffn, ffn, ffn, MTOK, FFdim, Hdim, 1);
        tf32_gemm_kernel<<<gH, 128>>>(ffn,
                                      W2 + (size_t)l * FFdim * Hdim, W2 + (size_t)l * FFdim * Hdim, W2 + (size_t)l * FFdim * Hdim,
                                      b2 + wH, b2 + wH, b2 + wH,
                                      q, q, q, MTOK, Hdim, FFdim, 0);
        add_ln_kernel<<<MTOK, 256>>>(x, q, ln2_g + wH, ln2_b + wH);
    }

    float* out = (float*)d_out;
    heads_kernel<<<MTOK, 256>>>(x, W_ent, b_ent, W_rel, b_rel, out);
    relation_kernel<<<MTOK, 256>>>(out + (size_t)MTOK * NEnt);
}